// round 8
// baseline (speedup 1.0000x reference)
#include <cuda_runtime.h>
#include <math.h>
#include <stdint.h>

#define BN_EPS 1e-5f

// Problem constants: B=32, F=26, O=20, IN=2048, G=512, FO=520, M=16640
#define MTOT 16640
#define NTOT 1024
#define KTOT 2048
#define FO   520
#define GDIM 512

// Scratch: Y = [rel_region | tem_region] : [16640, 1024] fp32 (68 MB)
__device__ float g_Y[(size_t)MTOT * NTOT];
__device__ float g_tsum[MTOT];

// ===========================================================================
// Helpers
// ===========================================================================
__device__ __forceinline__ uint32_t smem_u32(const void* p) {
    uint32_t a;
    asm("{ .reg .u64 t; cvta.to.shared.u64 t, %1; cvt.u32.u64 %0, t; }"
        : "=r"(a) : "l"(p));
    return a;
}

#define CP_ASYNC16(dst, src) \
    asm volatile("cp.async.cg.shared.global [%0], [%1], 16;" \
                 :: "r"(dst), "l"(src) : "memory")
#define CP_COMMIT() asm volatile("cp.async.commit_group;" ::: "memory")
#define CP_WAIT(n)  asm volatile("cp.async.wait_group %0;" :: "n"(n) : "memory")

#define LDSM_X4(r0, r1, r2, r3, addr) \
    asm volatile("ldmatrix.sync.aligned.m8n8.x4.shared.b16 {%0,%1,%2,%3}, [%4];" \
                 : "=r"(r0), "=r"(r1), "=r"(r2), "=r"(r3) : "r"(addr))

// mma.sync tf32: operand regs carry raw fp32 bits; HW truncates low mantissa.
__device__ __forceinline__ void mma_tf32(float* c, const uint32_t* a,
                                         const uint32_t* b) {
    asm volatile(
        "mma.sync.aligned.m16n8k8.row.col.f32.tf32.tf32.f32 "
        "{%0,%1,%2,%3}, {%4,%5,%6,%7}, {%8,%9}, {%0,%1,%2,%3};"
        : "+f"(c[0]), "+f"(c[1]), "+f"(c[2]), "+f"(c[3])
        : "r"(a[0]), "r"(a[1]), "r"(a[2]), "r"(a[3]),
          "r"(b[0]), "r"(b[1]));
}

// ===========================================================================
// temsum: g_tsum[row] = sum_k tem_feats[row, k]
// ===========================================================================
__global__ __launch_bounds__(128) void temsum_kernel(const float* __restrict__ tem)
{
    const int row = blockIdx.x;
    const float* p = tem + (size_t)row * FO;
    float s = 0.f;
    #pragma unroll
    for (int i = 0; i < 4; i++) s += p[threadIdx.x + i * 128];
    if (threadIdx.x < 8) s += p[512 + threadIdx.x];
    __shared__ float red[128];
    red[threadIdx.x] = s;
    __syncthreads();
    #pragma unroll
    for (int off = 64; off > 0; off >>= 1) {
        if (threadIdx.x < off) red[threadIdx.x] += red[threadIdx.x + off];
        __syncthreads();
    }
    if (threadIdx.x == 0) g_tsum[row] = red[0];
}

// ===========================================================================
// GEMM1 (mma.sync tf32, LDSM, raw fp32): Y[m,n] = sum_k A[m,k]*W[n,k] + b[n]
// Block 128x256, BK=16, 4-stage cp.async, 256 thr; warp grid 2x4, tile 64x64.
// ===========================================================================
#define G1_BM 128
#define G1_BN 256
#define G1_BK 16
#define G1_STAGES 4
#define G1_LDS 20
#define G1_ASTG (G1_BM * G1_LDS)      // 2560 floats
#define G1_BSTG (G1_BN * G1_LDS)      // 5120 floats
#define G1_KT (KTOT / G1_BK)          // 128

__global__ __launch_bounds__(256, 1) void gemm1_mma_kernel(
    const float* __restrict__ A,
    const float* __restrict__ relW, const float* __restrict__ relb,
    const float* __restrict__ temW, const float* __restrict__ temb)
{
    extern __shared__ float sm[];
    float* As = sm;                              // [STAGES][128][20]
    float* Bs = sm + G1_STAGES * G1_ASTG;        // [STAGES][256][20]
    __shared__ float sbias[G1_BN];

    const int tid  = threadIdx.x;
    const int wid  = tid >> 5;
    const int lane = tid & 31;
    const int m0 = blockIdx.y * G1_BM;
    const int n0 = blockIdx.x * G1_BN;
    const bool isTem = (n0 >= GDIM);

    const float* Bmat = isTem ? temW : relW;
    const int nloc = isTem ? (n0 - GDIM) : n0;

    sbias[tid] = isTem ? temb[nloc + tid] : relb[nloc + tid];

    // A staging: thread -> (row=tid>>1, chunk=(tid&1)*8): 2x cp.async16
    const int aRow = tid >> 1;
    const int aCol = (tid & 1) * 8;
    const float* gA = A + (size_t)(m0 + aRow) * KTOT + aCol;
    const uint32_t sA = smem_u32(As) + ((aRow * G1_LDS + aCol) << 2);
    // B staging: thread -> row=tid, 16 floats: 4x cp.async16
    const float* gB = Bmat + (size_t)(nloc + tid) * KTOT;
    const uint32_t sB = smem_u32(Bs) + ((tid * G1_LDS) << 2);

    const uint32_t aStg = G1_ASTG << 2;
    const uint32_t bStg = G1_BSTG << 2;

    const int wm = (wid >> 2) * 64;      // 2 M warps
    const int wn = (wid & 3) * 64;       // 4 N warps, 64 wide
    const int gr = lane >> 2;
    const int gc = lane & 3;

    // LDSM offsets (bytes, rel. to stage base)
    uint32_t aoff[4], boff[4];
    #pragma unroll
    for (int i = 0; i < 4; i++)
        aoff[i] = (uint32_t)(((wm + i * 16 + (lane & 15)) * G1_LDS
                              + ((lane >> 4) << 2)) << 2);
    #pragma unroll
    for (int jp = 0; jp < 4; jp++)
        boff[jp] = (uint32_t)(((wn + jp * 16 + (lane & 7) + ((lane >> 4) & 1) * 8)
                               * G1_LDS + (((lane >> 3) & 1) << 2)) << 2);

    const uint32_t aSm = smem_u32(As);
    const uint32_t bSm = smem_u32(Bs);

    float acc[4][8][4];
    #pragma unroll
    for (int i = 0; i < 4; i++)
        #pragma unroll
        for (int j = 0; j < 8; j++)
            #pragma unroll
            for (int r = 0; r < 4; r++) acc[i][j][r] = 0.f;

    #pragma unroll
    for (int s = 0; s < G1_STAGES - 1; s++) {
        const float* pa = gA + s * G1_BK;
        const float* pb = gB + s * G1_BK;
        CP_ASYNC16(sA + s * aStg,      pa);
        CP_ASYNC16(sA + s * aStg + 16, pa + 4);
        CP_ASYNC16(sB + s * bStg,      pb);
        CP_ASYNC16(sB + s * bStg + 16, pb + 4);
        CP_ASYNC16(sB + s * bStg + 32, pb + 8);
        CP_ASYNC16(sB + s * bStg + 48, pb + 12);
        CP_COMMIT();
    }

    #pragma unroll 1
    for (int kt = 0; kt < G1_KT; kt++) {
        CP_WAIT(G1_STAGES - 2);
        __syncthreads();

        if (kt + G1_STAGES - 1 < G1_KT) {
            const int s = (kt + G1_STAGES - 1) & (G1_STAGES - 1);
            const float* pa = gA + (kt + G1_STAGES - 1) * G1_BK;
            const float* pb = gB + (kt + G1_STAGES - 1) * G1_BK;
            CP_ASYNC16(sA + s * aStg,      pa);
            CP_ASYNC16(sA + s * aStg + 16, pa + 4);
            CP_ASYNC16(sB + s * bStg,      pb);
            CP_ASYNC16(sB + s * bStg + 16, pb + 4);
            CP_ASYNC16(sB + s * bStg + 32, pb + 8);
            CP_ASYNC16(sB + s * bStg + 48, pb + 12);
        }
        CP_COMMIT();

        const int s = kt & (G1_STAGES - 1);
        const uint32_t aBase = aSm + s * aStg;
        const uint32_t bBase = bSm + s * bStg;

        #pragma unroll
        for (int ks = 0; ks < 2; ks++) {
            const uint32_t kbB = (ks * 8) << 2;
            uint32_t af[4][4], bf[8][2];
            #pragma unroll
            for (int jp = 0; jp < 4; jp++)
                LDSM_X4(bf[2 * jp][0], bf[2 * jp][1],
                        bf[2 * jp + 1][0], bf[2 * jp + 1][1],
                        bBase + boff[jp] + kbB);
            #pragma unroll
            for (int i = 0; i < 4; i++)
                LDSM_X4(af[i][0], af[i][1], af[i][2], af[i][3],
                        aBase + aoff[i] + kbB);
            #pragma unroll
            for (int i = 0; i < 4; i++)
                #pragma unroll
                for (int j = 0; j < 8; j++)
                    mma_tf32(acc[i][j], af[i], bf[j]);
        }
    }

    __syncthreads();

    // Epilogue: +bias -> g_Y
    #pragma unroll
    for (int i = 0; i < 4; i++) {
        const int r0 = m0 + wm + i * 16 + gr;
        #pragma unroll
        for (int j = 0; j < 8; j++) {
            const int cl = wn + j * 8 + 2 * gc;
            float2 v0, v1;
            v0.x = acc[i][j][0] + sbias[cl];
            v0.y = acc[i][j][1] + sbias[cl + 1];
            v1.x = acc[i][j][2] + sbias[cl];
            v1.y = acc[i][j][3] + sbias[cl + 1];
            *reinterpret_cast<float2*>(g_Y + (size_t)r0 * NTOT + n0 + cl) = v0;
            *reinterpret_cast<float2*>(g_Y + (size_t)(r0 + 8) * NTOT + n0 + cl) = v1;
        }
    }
}

// ---------------------------------------------------------------------------
// rel epilogue
// ---------------------------------------------------------------------------
__global__ __launch_bounds__(128) void rel_kernel(
    const int* __restrict__ rel_feats,
    const float* __restrict__ rel_emb,
    const float* __restrict__ bn_w, const float* __restrict__ bn_b,
    const float* __restrict__ bn_rm, const float* __restrict__ bn_rv,
    float* __restrict__ out)
{
    const int row = blockIdx.x;
    const int g = threadIdx.x;
    __shared__ int srel[20];
    if (g < 20) srel[g] = rel_feats[(size_t)row * 20 + g];
    __syncthreads();

    float msum = 0.f;
    float a0 = 0.f, a1 = 0.f, a2 = 0.f, a3 = 0.f;
    #pragma unroll
    for (int j = 0; j < 20; j++) {
        int r = srel[j];
        if (r > 0) {
            msum += 1.f;
            const float* e = rel_emb + (size_t)r * GDIM;
            a0 += e[g];
            a1 += e[g + 128];
            a2 += e[g + 256];
            a3 += e[g + 384];
        }
    }

    const int c = row % FO;
    const float inv = bn_w[c] / sqrtf(bn_rv[c] + BN_EPS);
    const float rmv = bn_rm[c], bbv = bn_b[c];
    const float* yrow = g_Y + (size_t)row * NTOT;
    float* orow = out + (size_t)row * NTOT;

    float accs[4] = {a0, a1, a2, a3};
    #pragma unroll
    for (int i = 0; i < 4; i++) {
        int gg = g + i * 128;
        float val = (accs[i] + yrow[gg] * msum) / msum;
        float t = tanhf(val);
        orow[gg] = (t - rmv) * inv + bbv;
    }
}

// ===========================================================================
// GEMM2 (mma.sync tf32, A via LDSM, raw fp32): per batch b:
//   C[m,n] = sum_k tem[b][m,k] * g_Y_tem[b*520+k, n]
// Block 64x128, BK=8, 3-stage cp.async, 256 thr (8 warps, 32x32).
// ===========================================================================
#define G2_BM 64
#define G2_BN 128
#define G2_BK 8
#define G2_STAGES 3
#define G2_LDA 12
#define G2_LDB 136
#define G2_ASTG (G2_BM * G2_LDA)
#define G2_BSTG (G2_BK * G2_LDB)
#define G2_KT (FO / G2_BK)

__global__ __launch_bounds__(256) void gemm2_mma_kernel(
    const float* __restrict__ tem,
    const float* __restrict__ bn_w, const float* __restrict__ bn_b,
    const float* __restrict__ bn_rm, const float* __restrict__ bn_rv,
    float* __restrict__ out)
{
    __shared__ float As[G2_STAGES * G2_ASTG];
    __shared__ float Bs[G2_STAGES * G2_BSTG];

    const int b  = blockIdx.z;
    const int m0 = blockIdx.y * G2_BM;
    const int nb0 = blockIdx.x * G2_BN;

    const int tid  = threadIdx.x;
    const int wid  = tid >> 5;
    const int lane = tid & 31;

    const int aRow = tid >> 1;
    const int aHalf = (tid & 1) * 4;
    const int aRowG = (m0 + aRow < FO) ? (m0 + aRow) : (FO - 1);
    const float* gA = tem + (size_t)b * FO * FO + (size_t)aRowG * FO + aHalf;
    const uint32_t sA = smem_u32(As) + ((aRow * G2_LDA + aHalf) << 2);

    const int bRow = tid >> 5;
    const int bCol = (tid & 31) * 4;
    const float* gB = g_Y + GDIM + nb0 + bCol + (size_t)(b * FO + bRow) * NTOT;
    const uint32_t sB = smem_u32(Bs) + ((bRow * G2_LDB + bCol) << 2);

    const uint32_t aStg = G2_ASTG << 2;
    const uint32_t bStg = G2_BSTG << 2;

    const int wm = (wid >> 2) * 32;
    const int wn = (wid & 3) * 32;
    const int gr = lane >> 2;
    const int gc = lane & 3;

    uint32_t aoff[2];
    #pragma unroll
    for (int i = 0; i < 2; i++)
        aoff[i] = (uint32_t)(((wm + i * 16 + (lane & 15)) * G2_LDA
                              + ((lane >> 4) << 2)) << 2);
    const uint32_t aSm = smem_u32(As);

    float acc[2][4][4];
    #pragma unroll
    for (int i = 0; i < 2; i++)
        #pragma unroll
        for (int j = 0; j < 4; j++)
            #pragma unroll
            for (int r = 0; r < 4; r++) acc[i][j][r] = 0.f;

    #pragma unroll
    for (int s = 0; s < G2_STAGES - 1; s++) {
        if (tid < 128) CP_ASYNC16(sA + s * aStg, gA + s * G2_BK);
        CP_ASYNC16(sB + s * bStg, gB + (size_t)s * G2_BK * NTOT);
        CP_COMMIT();
    }

    #pragma unroll 1
    for (int kt = 0; kt < G2_KT; kt++) {
        CP_WAIT(G2_STAGES - 2);
        __syncthreads();

        if (kt + G2_STAGES - 1 < G2_KT) {
            const int s = (kt + G2_STAGES - 1) % G2_STAGES;
            const int kk = (kt + G2_STAGES - 1) * G2_BK;
            if (tid < 128) CP_ASYNC16(sA + s * aStg, gA + kk);
            CP_ASYNC16(sB + s * bStg, gB + (size_t)kk * NTOT);
        }
        CP_COMMIT();

        const int s = kt % G2_STAGES;
        const uint32_t aBase = aSm + s * aStg;
        const uint32_t* Bst = reinterpret_cast<const uint32_t*>(Bs + s * G2_BSTG);

        uint32_t af[2][4];
        #pragma unroll
        for (int i = 0; i < 2; i++)
            LDSM_X4(af[i][0], af[i][1], af[i][2], af[i][3], aBase + aoff[i]);
        uint32_t bf[4][2];
        #pragma unroll
        for (int j = 0; j < 4; j++) {
            const uint32_t* p = Bst + gc * G2_LDB + wn + j * 8 + gr;
            bf[j][0] = p[0];
            bf[j][1] = p[4 * G2_LDB];
        }
        #pragma unroll
        for (int i = 0; i < 2; i++)
            #pragma unroll
            for (int j = 0; j < 4; j++)
                mma_tf32(acc[i][j], af[i], bf[j]);
    }

    #pragma unroll
    for (int i = 0; i < 2; i++) {
        #pragma unroll
        for (int half = 0; half < 2; half++) {
            const int m = m0 + wm + i * 16 + gr + half * 8;
            if (m < FO) {
                const float tsum = g_tsum[b * FO + m];
                const float inv = bn_w[m] / sqrtf(bn_rv[m] + BN_EPS);
                const float rmv = bn_rm[m], bbv = bn_b[m];
                float* orow = out + (size_t)(b * FO + m) * NTOT + GDIM + nb0;
                #pragma unroll
                for (int j = 0; j < 4; j++) {
                    const int cl = wn + j * 8 + 2 * gc;
                    float2 v;
                    v.x = (tanhf(acc[i][j][half * 2 + 0] / tsum) - rmv) * inv + bbv;
                    v.y = (tanhf(acc[i][j][half * 2 + 1] / tsum) - rmv) * inv + bbv;
                    *reinterpret_cast<float2*>(orow + cl) = v;
                }
            }
        }
    }
}

// ---------------------------------------------------------------------------
extern "C" void kernel_launch(void* const* d_in, const int* in_sizes, int n_in,
                              void* d_out, int out_size)
{
    const float* region   = (const float*)d_in[0];
    // d_in[1] = region_masks (unused by the reference math)
    const int*   relF     = (const int*)d_in[2];
    const float* tem      = (const float*)d_in[3];
    const float* relW     = (const float*)d_in[4];
    const float* relb     = (const float*)d_in[5];
    const float* rel_emb  = (const float*)d_in[6];
    const float* temW     = (const float*)d_in[7];
    const float* temb     = (const float*)d_in[8];
    const float* bn_w     = (const float*)d_in[9];
    const float* bn_b     = (const float*)d_in[10];
    const float* bn_rm    = (const float*)d_in[11];
    const float* bn_rv    = (const float*)d_in[12];
    float* out = (float*)d_out;

    temsum_kernel<<<MTOT, 128>>>(tem);

    const int g1_smem = G1_STAGES * (G1_ASTG + G1_BSTG) * sizeof(float); // 122880
    cudaFuncSetAttribute(gemm1_mma_kernel,
                         cudaFuncAttributeMaxDynamicSharedMemorySize, g1_smem);

    dim3 g1(NTOT / G1_BN, MTOT / G1_BM);        // (4, 130)
    gemm1_mma_kernel<<<g1, 256, g1_smem>>>(region, relW, relb, temW, temb);

    rel_kernel<<<MTOT, 128>>>(relF, rel_emb, bn_w, bn_b, bn_rm, bn_rv, out);

    dim3 g2(GDIM / G2_BN, (FO + G2_BM - 1) / G2_BM, 32);   // (4, 9, 32)
    gemm2_mma_kernel<<<g2, 256>>>(tem, bn_w, bn_b, bn_rm, bn_rv, out);
}

// round 9
// speedup vs baseline: 1.0098x; 1.0098x over previous
#include <cuda_runtime.h>
#include <math.h>
#include <stdint.h>

#define BN_EPS 1e-5f

// Problem constants: B=32, F=26, O=20, IN=2048, G=512, FO=520, M=16640
#define MTOT 16640
#define NTOT 1024
#define KTOT 2048
#define FO   520
#define GDIM 512

// Scratch: Y = [rel_region | tem_region] : [16640, 1024] fp32 (68 MB)
__device__ float g_Y[(size_t)MTOT * NTOT];
__device__ float g_tsum[MTOT];

// ===========================================================================
// Helpers
// ===========================================================================
__device__ __forceinline__ uint32_t smem_u32(const void* p) {
    uint32_t a;
    asm("{ .reg .u64 t; cvta.to.shared.u64 t, %1; cvt.u32.u64 %0, t; }"
        : "=r"(a) : "l"(p));
    return a;
}

#define CP_ASYNC16(dst, src) \
    asm volatile("cp.async.cg.shared.global [%0], [%1], 16;" \
                 :: "r"(dst), "l"(src) : "memory")
#define CP_COMMIT() asm volatile("cp.async.commit_group;" ::: "memory")
#define CP_WAIT(n)  asm volatile("cp.async.wait_group %0;" :: "n"(n) : "memory")

#define LDSM_X4(r0, r1, r2, r3, addr) \
    asm volatile("ldmatrix.sync.aligned.m8n8.x4.shared.b16 {%0,%1,%2,%3}, [%4];" \
                 : "=r"(r0), "=r"(r1), "=r"(r2), "=r"(r3) : "r"(addr))

// mma.sync tf32: operand regs carry raw fp32 bits; HW truncates low mantissa.
__device__ __forceinline__ void mma_tf32(float* c, const uint32_t* a,
                                         const uint32_t* b) {
    asm volatile(
        "mma.sync.aligned.m16n8k8.row.col.f32.tf32.tf32.f32 "
        "{%0,%1,%2,%3}, {%4,%5,%6,%7}, {%8,%9}, {%0,%1,%2,%3};"
        : "+f"(c[0]), "+f"(c[1]), "+f"(c[2]), "+f"(c[3])
        : "r"(a[0]), "r"(a[1]), "r"(a[2]), "r"(a[3]),
          "r"(b[0]), "r"(b[1]));
}

// ===========================================================================
// temsum: g_tsum[row] = sum_k tem_feats[row, k]
// ===========================================================================
__global__ __launch_bounds__(128) void temsum_kernel(const float* __restrict__ tem)
{
    const int row = blockIdx.x;
    const float* p = tem + (size_t)row * FO;
    float s = 0.f;
    #pragma unroll
    for (int i = 0; i < 4; i++) s += p[threadIdx.x + i * 128];
    if (threadIdx.x < 8) s += p[512 + threadIdx.x];
    __shared__ float red[128];
    red[threadIdx.x] = s;
    __syncthreads();
    #pragma unroll
    for (int off = 64; off > 0; off >>= 1) {
        if (threadIdx.x < off) red[threadIdx.x] += red[threadIdx.x + off];
        __syncthreads();
    }
    if (threadIdx.x == 0) g_tsum[row] = red[0];
}

// ===========================================================================
// GEMM1 (mma.sync tf32, LDSM, raw fp32): Y[m,n] = sum_k A[m,k]*W[n,k] + b[n]
// Block 128x128, BK=16, 4-stage cp.async, 128 thr; warp grid 2x2, tile 64x64.
// 2 CTAs/SM (82KB smem each) -> barriers hidden by the co-resident CTA.
// ===========================================================================
#define G1_BM 128
#define G1_BN 128
#define G1_BK 16
#define G1_STAGES 4
#define G1_LDS 20
#define G1_STG_F (G1_BM * G1_LDS)       // 2560 floats per operand per stage
#define G1_KT (KTOT / G1_BK)            // 128

__global__ __launch_bounds__(128, 2) void gemm1_mma_kernel(
    const float* __restrict__ A,
    const float* __restrict__ relW, const float* __restrict__ relb,
    const float* __restrict__ temW, const float* __restrict__ temb)
{
    extern __shared__ float sm[];
    float* As = sm;                          // [STAGES][128][20]
    float* Bs = sm + G1_STAGES * G1_STG_F;   // [STAGES][128][20]
    __shared__ float sbias[G1_BN];

    const int tid  = threadIdx.x;
    const int wid  = tid >> 5;
    const int lane = tid & 31;
    const int m0 = blockIdx.y * G1_BM;
    const int n0 = blockIdx.x * G1_BN;
    const bool isTem = (n0 >= GDIM);

    const float* Bmat = isTem ? temW : relW;
    const int nloc = isTem ? (n0 - GDIM) : n0;

    sbias[tid] = isTem ? temb[nloc + tid] : relb[nloc + tid];

    // Staging: thread tid owns row tid of each operand (16 floats = 4 x 16B)
    const float* gA = A + (size_t)(m0 + tid) * KTOT;
    const float* gB = Bmat + (size_t)(nloc + tid) * KTOT;
    const uint32_t sA = smem_u32(As) + ((tid * G1_LDS) << 2);
    const uint32_t sB = smem_u32(Bs) + ((tid * G1_LDS) << 2);
    const uint32_t stgB = G1_STG_F << 2;

    // Warp grid 2x2, warp tile 64x64
    const int wm = (wid >> 1) * 64;
    const int wn = (wid & 1) * 64;
    const int gr = lane >> 2;
    const int gc = lane & 3;

    // LDSM offsets (bytes, rel. to stage base)
    uint32_t aoff[4], boff[4];
    #pragma unroll
    for (int i = 0; i < 4; i++)
        aoff[i] = (uint32_t)(((wm + i * 16 + (lane & 15)) * G1_LDS
                              + ((lane >> 4) << 2)) << 2);
    #pragma unroll
    for (int jp = 0; jp < 4; jp++)
        boff[jp] = (uint32_t)(((wn + jp * 16 + (lane & 7) + ((lane >> 4) & 1) * 8)
                               * G1_LDS + (((lane >> 3) & 1) << 2)) << 2);

    const uint32_t aSm = smem_u32(As);
    const uint32_t bSm = smem_u32(Bs);

    float acc[4][8][4];
    #pragma unroll
    for (int i = 0; i < 4; i++)
        #pragma unroll
        for (int j = 0; j < 8; j++)
            #pragma unroll
            for (int r = 0; r < 4; r++) acc[i][j][r] = 0.f;

    #pragma unroll
    for (int s = 0; s < G1_STAGES - 1; s++) {
        const float* pa = gA + s * G1_BK;
        const float* pb = gB + s * G1_BK;
        CP_ASYNC16(sA + s * stgB,      pa);
        CP_ASYNC16(sA + s * stgB + 16, pa + 4);
        CP_ASYNC16(sA + s * stgB + 32, pa + 8);
        CP_ASYNC16(sA + s * stgB + 48, pa + 12);
        CP_ASYNC16(sB + s * stgB,      pb);
        CP_ASYNC16(sB + s * stgB + 16, pb + 4);
        CP_ASYNC16(sB + s * stgB + 32, pb + 8);
        CP_ASYNC16(sB + s * stgB + 48, pb + 12);
        CP_COMMIT();
    }

    #pragma unroll 1
    for (int kt = 0; kt < G1_KT; kt++) {
        CP_WAIT(G1_STAGES - 2);
        __syncthreads();

        if (kt + G1_STAGES - 1 < G1_KT) {
            const int s = (kt + G1_STAGES - 1) & (G1_STAGES - 1);
            const float* pa = gA + (kt + G1_STAGES - 1) * G1_BK;
            const float* pb = gB + (kt + G1_STAGES - 1) * G1_BK;
            CP_ASYNC16(sA + s * stgB,      pa);
            CP_ASYNC16(sA + s * stgB + 16, pa + 4);
            CP_ASYNC16(sA + s * stgB + 32, pa + 8);
            CP_ASYNC16(sA + s * stgB + 48, pa + 12);
            CP_ASYNC16(sB + s * stgB,      pb);
            CP_ASYNC16(sB + s * stgB + 16, pb + 4);
            CP_ASYNC16(sB + s * stgB + 32, pb + 8);
            CP_ASYNC16(sB + s * stgB + 48, pb + 12);
        }
        CP_COMMIT();

        const int s = kt & (G1_STAGES - 1);
        const uint32_t aBase = aSm + s * stgB;
        const uint32_t bBase = bSm + s * stgB;

        #pragma unroll
        for (int ks = 0; ks < 2; ks++) {
            const uint32_t kbB = (ks * 8) << 2;
            uint32_t af[4][4], bf[8][2];
            #pragma unroll
            for (int jp = 0; jp < 4; jp++)
                LDSM_X4(bf[2 * jp][0], bf[2 * jp][1],
                        bf[2 * jp + 1][0], bf[2 * jp + 1][1],
                        bBase + boff[jp] + kbB);
            #pragma unroll
            for (int i = 0; i < 4; i++)
                LDSM_X4(af[i][0], af[i][1], af[i][2], af[i][3],
                        aBase + aoff[i] + kbB);
            #pragma unroll
            for (int i = 0; i < 4; i++)
                #pragma unroll
                for (int j = 0; j < 8; j++)
                    mma_tf32(acc[i][j], af[i], bf[j]);
        }
    }

    __syncthreads();

    // Epilogue: +bias -> g_Y
    #pragma unroll
    for (int i = 0; i < 4; i++) {
        const int r0 = m0 + wm + i * 16 + gr;
        #pragma unroll
        for (int j = 0; j < 8; j++) {
            const int cl = wn + j * 8 + 2 * gc;
            float2 v0, v1;
            v0.x = acc[i][j][0] + sbias[cl];
            v0.y = acc[i][j][1] + sbias[cl + 1];
            v1.x = acc[i][j][2] + sbias[cl];
            v1.y = acc[i][j][3] + sbias[cl + 1];
            *reinterpret_cast<float2*>(g_Y + (size_t)r0 * NTOT + n0 + cl) = v0;
            *reinterpret_cast<float2*>(g_Y + (size_t)(r0 + 8) * NTOT + n0 + cl) = v1;
        }
    }
}

// ---------------------------------------------------------------------------
// rel epilogue
// ---------------------------------------------------------------------------
__global__ __launch_bounds__(128) void rel_kernel(
    const int* __restrict__ rel_feats,
    const float* __restrict__ rel_emb,
    const float* __restrict__ bn_w, const float* __restrict__ bn_b,
    const float* __restrict__ bn_rm, const float* __restrict__ bn_rv,
    float* __restrict__ out)
{
    const int row = blockIdx.x;
    const int g = threadIdx.x;
    __shared__ int srel[20];
    if (g < 20) srel[g] = rel_feats[(size_t)row * 20 + g];
    __syncthreads();

    float msum = 0.f;
    float a0 = 0.f, a1 = 0.f, a2 = 0.f, a3 = 0.f;
    #pragma unroll
    for (int j = 0; j < 20; j++) {
        int r = srel[j];
        if (r > 0) {
            msum += 1.f;
            const float* e = rel_emb + (size_t)r * GDIM;
            a0 += e[g];
            a1 += e[g + 128];
            a2 += e[g + 256];
            a3 += e[g + 384];
        }
    }

    const int c = row % FO;
    const float inv = bn_w[c] / sqrtf(bn_rv[c] + BN_EPS);
    const float rmv = bn_rm[c], bbv = bn_b[c];
    const float* yrow = g_Y + (size_t)row * NTOT;
    float* orow = out + (size_t)row * NTOT;

    float accs[4] = {a0, a1, a2, a3};
    #pragma unroll
    for (int i = 0; i < 4; i++) {
        int gg = g + i * 128;
        float val = (accs[i] + yrow[gg] * msum) / msum;
        float t = tanhf(val);
        orow[gg] = (t - rmv) * inv + bbv;
    }
}

// ===========================================================================
// GEMM2 (mma.sync tf32, A via LDSM, raw fp32): per batch b:
//   C[m,n] = sum_k tem[b][m,k] * g_Y_tem[b*520+k, n]
// Block 64x128, BK=8, 3-stage cp.async, 256 thr (8 warps, 32x32).
// ===========================================================================
#define G2_BM 64
#define G2_BN 128
#define G2_BK 8
#define G2_STAGES 3
#define G2_LDA 12
#define G2_LDB 136
#define G2_ASTG (G2_BM * G2_LDA)
#define G2_BSTG (G2_BK * G2_LDB)
#define G2_KT (FO / G2_BK)

__global__ __launch_bounds__(256) void gemm2_mma_kernel(
    const float* __restrict__ tem,
    const float* __restrict__ bn_w, const float* __restrict__ bn_b,
    const float* __restrict__ bn_rm, const float* __restrict__ bn_rv,
    float* __restrict__ out)
{
    __shared__ float As[G2_STAGES * G2_ASTG];
    __shared__ float Bs[G2_STAGES * G2_BSTG];

    const int b  = blockIdx.z;
    const int m0 = blockIdx.y * G2_BM;
    const int nb0 = blockIdx.x * G2_BN;

    const int tid  = threadIdx.x;
    const int wid  = tid >> 5;
    const int lane = tid & 31;

    const int aRow = tid >> 1;
    const int aHalf = (tid & 1) * 4;
    const int aRowG = (m0 + aRow < FO) ? (m0 + aRow) : (FO - 1);
    const float* gA = tem + (size_t)b * FO * FO + (size_t)aRowG * FO + aHalf;
    const uint32_t sA = smem_u32(As) + ((aRow * G2_LDA + aHalf) << 2);

    const int bRow = tid >> 5;
    const int bCol = (tid & 31) * 4;
    const float* gB = g_Y + GDIM + nb0 + bCol + (size_t)(b * FO + bRow) * NTOT;
    const uint32_t sB = smem_u32(Bs) + ((bRow * G2_LDB + bCol) << 2);

    const uint32_t aStg = G2_ASTG << 2;
    const uint32_t bStg = G2_BSTG << 2;

    const int wm = (wid >> 2) * 32;
    const int wn = (wid & 3) * 32;
    const int gr = lane >> 2;
    const int gc = lane & 3;

    uint32_t aoff[2];
    #pragma unroll
    for (int i = 0; i < 2; i++)
        aoff[i] = (uint32_t)(((wm + i * 16 + (lane & 15)) * G2_LDA
                              + ((lane >> 4) << 2)) << 2);
    const uint32_t aSm = smem_u32(As);

    float acc[2][4][4];
    #pragma unroll
    for (int i = 0; i < 2; i++)
        #pragma unroll
        for (int j = 0; j < 4; j++)
            #pragma unroll
            for (int r = 0; r < 4; r++) acc[i][j][r] = 0.f;

    #pragma unroll
    for (int s = 0; s < G2_STAGES - 1; s++) {
        if (tid < 128) CP_ASYNC16(sA + s * aStg, gA + s * G2_BK);
        CP_ASYNC16(sB + s * bStg, gB + (size_t)s * G2_BK * NTOT);
        CP_COMMIT();
    }

    #pragma unroll 1
    for (int kt = 0; kt < G2_KT; kt++) {
        CP_WAIT(G2_STAGES - 2);
        __syncthreads();

        if (kt + G2_STAGES - 1 < G2_KT) {
            const int s = (kt + G2_STAGES - 1) % G2_STAGES;
            const int kk = (kt + G2_STAGES - 1) * G2_BK;
            if (tid < 128) CP_ASYNC16(sA + s * aStg, gA + kk);
            CP_ASYNC16(sB + s * bStg, gB + (size_t)kk * NTOT);
        }
        CP_COMMIT();

        const int s = kt % G2_STAGES;
        const uint32_t aBase = aSm + s * aStg;
        const uint32_t* Bst = reinterpret_cast<const uint32_t*>(Bs + s * G2_BSTG);

        uint32_t af[2][4];
        #pragma unroll
        for (int i = 0; i < 2; i++)
            LDSM_X4(af[i][0], af[i][1], af[i][2], af[i][3], aBase + aoff[i]);
        uint32_t bf[4][2];
        #pragma unroll
        for (int j = 0; j < 4; j++) {
            const uint32_t* p = Bst + gc * G2_LDB + wn + j * 8 + gr;
            bf[j][0] = p[0];
            bf[j][1] = p[4 * G2_LDB];
        }
        #pragma unroll
        for (int i = 0; i < 2; i++)
            #pragma unroll
            for (int j = 0; j < 4; j++)
                mma_tf32(acc[i][j], af[i], bf[j]);
    }

    #pragma unroll
    for (int i = 0; i < 2; i++) {
        #pragma unroll
        for (int half = 0; half < 2; half++) {
            const int m = m0 + wm + i * 16 + gr + half * 8;
            if (m < FO) {
                const float tsum = g_tsum[b * FO + m];
                const float inv = bn_w[m] / sqrtf(bn_rv[m] + BN_EPS);
                const float rmv = bn_rm[m], bbv = bn_b[m];
                float* orow = out + (size_t)(b * FO + m) * NTOT + GDIM + nb0;
                #pragma unroll
                for (int j = 0; j < 4; j++) {
                    const int cl = wn + j * 8 + 2 * gc;
                    float2 v;
                    v.x = (tanhf(acc[i][j][half * 2 + 0] / tsum) - rmv) * inv + bbv;
                    v.y = (tanhf(acc[i][j][half * 2 + 1] / tsum) - rmv) * inv + bbv;
                    *reinterpret_cast<float2*>(orow + cl) = v;
                }
            }
        }
    }
}

// ---------------------------------------------------------------------------
extern "C" void kernel_launch(void* const* d_in, const int* in_sizes, int n_in,
                              void* d_out, int out_size)
{
    const float* region   = (const float*)d_in[0];
    // d_in[1] = region_masks (unused by the reference math)
    const int*   relF     = (const int*)d_in[2];
    const float* tem      = (const float*)d_in[3];
    const float* relW     = (const float*)d_in[4];
    const float* relb     = (const float*)d_in[5];
    const float* rel_emb  = (const float*)d_in[6];
    const float* temW     = (const float*)d_in[7];
    const float* temb     = (const float*)d_in[8];
    const float* bn_w     = (const float*)d_in[9];
    const float* bn_b     = (const float*)d_in[10];
    const float* bn_rm    = (const float*)d_in[11];
    const float* bn_rv    = (const float*)d_in[12];
    float* out = (float*)d_out;

    temsum_kernel<<<MTOT, 128>>>(tem);

    const int g1_smem = G1_STAGES * G1_STG_F * 2 * sizeof(float);  // 81920
    cudaFuncSetAttribute(gemm1_mma_kernel,
                         cudaFuncAttributeMaxDynamicSharedMemorySize, g1_smem);

    dim3 g1(NTOT / G1_BN, MTOT / G1_BM);        // (8, 130)
    gemm1_mma_kernel<<<g1, 128, g1_smem>>>(region, relW, relb, temW, temb);

    rel_kernel<<<MTOT, 128>>>(relF, rel_emb, bn_w, bn_b, bn_rm, bn_rv, out);

    dim3 g2(GDIM / G2_BN, (FO + G2_BM - 1) / G2_BM, 32);   // (4, 9, 32)
    gemm2_mma_kernel<<<g2, 256>>>(tem, bn_w, bn_b, bn_rm, bn_rv, out);
}

// round 10
// speedup vs baseline: 1.2463x; 1.2343x over previous
#include <cuda_runtime.h>
#include <math.h>
#include <stdint.h>

#define BN_EPS 1e-5f

// Problem constants: B=32, F=26, O=20, IN=2048, G=512, FO=520, M=16640
#define MTOT 16640
#define NTOT 1024
#define KTOT 2048
#define FO   520
#define GDIM 512

// Scratch: Y = [rel_region | tem_region] : [16640, 1024] fp32 (68 MB)
__device__ float g_Y[(size_t)MTOT * NTOT];
__device__ float g_tsum[MTOT];

// ===========================================================================
// Helpers
// ===========================================================================
__device__ __forceinline__ uint32_t smem_u32(const void* p) {
    uint32_t a;
    asm("{ .reg .u64 t; cvta.to.shared.u64 t, %1; cvt.u32.u64 %0, t; }"
        : "=r"(a) : "l"(p));
    return a;
}

#define CP_ASYNC16(dst, src) \
    asm volatile("cp.async.cg.shared.global [%0], [%1], 16;" \
                 :: "r"(dst), "l"(src) : "memory")
#define CP_COMMIT() asm volatile("cp.async.commit_group;" ::: "memory")
#define CP_WAIT(n)  asm volatile("cp.async.wait_group %0;" :: "n"(n) : "memory")

#define LDSM_X4(r0, r1, r2, r3, addr) \
    asm volatile("ldmatrix.sync.aligned.m8n8.x4.shared.b16 {%0,%1,%2,%3}, [%4];" \
                 : "=r"(r0), "=r"(r1), "=r"(r2), "=r"(r3) : "r"(addr))

// mma.sync tf32: operand regs carry raw fp32 bits; HW truncates low mantissa.
__device__ __forceinline__ void mma_tf32(float* c, const uint32_t* a,
                                         const uint32_t* b) {
    asm volatile(
        "mma.sync.aligned.m16n8k8.row.col.f32.tf32.tf32.f32 "
        "{%0,%1,%2,%3}, {%4,%5,%6,%7}, {%8,%9}, {%0,%1,%2,%3};"
        : "+f"(c[0]), "+f"(c[1]), "+f"(c[2]), "+f"(c[3])
        : "r"(a[0]), "r"(a[1]), "r"(a[2]), "r"(a[3]),
          "r"(b[0]), "r"(b[1]));
}

// ===========================================================================
// temsum: g_tsum[row] = sum_k tem_feats[row, k]
// ===========================================================================
__global__ __launch_bounds__(128) void temsum_kernel(const float* __restrict__ tem)
{
    const int row = blockIdx.x;
    const float* p = tem + (size_t)row * FO;
    float s = 0.f;
    #pragma unroll
    for (int i = 0; i < 4; i++) s += p[threadIdx.x + i * 128];
    if (threadIdx.x < 8) s += p[512 + threadIdx.x];
    __shared__ float red[128];
    red[threadIdx.x] = s;
    __syncthreads();
    #pragma unroll
    for (int off = 64; off > 0; off >>= 1) {
        if (threadIdx.x < off) red[threadIdx.x] += red[threadIdx.x + off];
        __syncthreads();
    }
    if (threadIdx.x == 0) g_tsum[row] = red[0];
}

// ===========================================================================
// GEMM1 (EXACT R7 winner): Y[m,n] = sum_k A[m,k]*W[n,k] + b[n]
// Block 128x128, BK=16, 4-stage cp.async, 256 thr (8 warps, 64x32).
// ===========================================================================
#define G1_BM 128
#define G1_BN 128
#define G1_BK 16
#define G1_STAGES 4
#define G1_LDS 20
#define G1_STG_F (G1_BM * G1_LDS)
#define G1_KT (KTOT / G1_BK)

__global__ __launch_bounds__(256) void gemm1_mma_kernel(
    const float* __restrict__ A,
    const float* __restrict__ relW, const float* __restrict__ relb,
    const float* __restrict__ temW, const float* __restrict__ temb)
{
    extern __shared__ float sm[];
    float* As = sm;
    float* Bs = sm + G1_STAGES * G1_STG_F;
    __shared__ float sbias[G1_BN];

    const int tid  = threadIdx.x;
    const int wid  = tid >> 5;
    const int lane = tid & 31;
    const int m0 = blockIdx.y * G1_BM;
    const int n0 = blockIdx.x * G1_BN;
    const bool isTem = (n0 >= GDIM);

    const float* Bmat = isTem ? temW : relW;
    const int nloc = isTem ? (n0 - GDIM) : n0;

    if (tid < G1_BN)
        sbias[tid] = isTem ? temb[nloc + tid] : relb[nloc + tid];

    const int ldRow = tid >> 1;
    const int ldCol = (tid & 1) * 8;
    const float* gA = A + (size_t)(m0 + ldRow) * KTOT + ldCol;
    const float* gB = Bmat + (size_t)(nloc + ldRow) * KTOT + ldCol;
    const uint32_t sA = smem_u32(As) + ((ldRow * G1_LDS + ldCol) << 2);
    const uint32_t sB = smem_u32(Bs) + ((ldRow * G1_LDS + ldCol) << 2);
    const uint32_t stgB = G1_STG_F << 2;

    const int wm = (wid >> 2) * 64;
    const int wn = (wid & 3) * 32;
    const int gr = lane >> 2;
    const int gc = lane & 3;

    uint32_t aoff[4], boff[2];
    #pragma unroll
    for (int i = 0; i < 4; i++)
        aoff[i] = (uint32_t)(((wm + i * 16 + (lane & 15)) * G1_LDS
                              + ((lane >> 4) << 2)) << 2);
    #pragma unroll
    for (int jp = 0; jp < 2; jp++)
        boff[jp] = (uint32_t)(((wn + jp * 16 + (lane & 7) + ((lane >> 4) & 1) * 8)
                               * G1_LDS + (((lane >> 3) & 1) << 2)) << 2);

    const uint32_t aSm = smem_u32(As);
    const uint32_t bSm = smem_u32(Bs);

    float acc[4][4][4];
    #pragma unroll
    for (int i = 0; i < 4; i++)
        #pragma unroll
        for (int j = 0; j < 4; j++)
            #pragma unroll
            for (int r = 0; r < 4; r++) acc[i][j][r] = 0.f;

    #pragma unroll
    for (int s = 0; s < G1_STAGES - 1; s++) {
        const float* pa = gA + s * G1_BK;
        const float* pb = gB + s * G1_BK;
        CP_ASYNC16(sA + s * stgB,      pa);
        CP_ASYNC16(sA + s * stgB + 16, pa + 4);
        CP_ASYNC16(sB + s * stgB,      pb);
        CP_ASYNC16(sB + s * stgB + 16, pb + 4);
        CP_COMMIT();
    }

    #pragma unroll 1
    for (int kt = 0; kt < G1_KT; kt++) {
        CP_WAIT(G1_STAGES - 2);
        __syncthreads();

        if (kt + G1_STAGES - 1 < G1_KT) {
            const int s = (kt + G1_STAGES - 1) & (G1_STAGES - 1);
            const float* pa = gA + (kt + G1_STAGES - 1) * G1_BK;
            const float* pb = gB + (kt + G1_STAGES - 1) * G1_BK;
            CP_ASYNC16(sA + s * stgB,      pa);
            CP_ASYNC16(sA + s * stgB + 16, pa + 4);
            CP_ASYNC16(sB + s * stgB,      pb);
            CP_ASYNC16(sB + s * stgB + 16, pb + 4);
        }
        CP_COMMIT();

        const int s = kt & (G1_STAGES - 1);
        const uint32_t aBase = aSm + s * stgB;
        const uint32_t bBase = bSm + s * stgB;

        #pragma unroll
        for (int ks = 0; ks < 2; ks++) {
            const uint32_t kbB = (ks * 8) << 2;
            uint32_t af[4][4], bf[4][2];
            #pragma unroll
            for (int jp = 0; jp < 2; jp++)
                LDSM_X4(bf[2 * jp][0], bf[2 * jp][1],
                        bf[2 * jp + 1][0], bf[2 * jp + 1][1],
                        bBase + boff[jp] + kbB);
            #pragma unroll
            for (int i = 0; i < 4; i++)
                LDSM_X4(af[i][0], af[i][1], af[i][2], af[i][3],
                        aBase + aoff[i] + kbB);
            #pragma unroll
            for (int i = 0; i < 4; i++)
                #pragma unroll
                for (int j = 0; j < 4; j++)
                    mma_tf32(acc[i][j], af[i], bf[j]);
        }
    }

    __syncthreads();

    #pragma unroll
    for (int i = 0; i < 4; i++) {
        const int r0 = m0 + wm + i * 16 + gr;
        #pragma unroll
        for (int j = 0; j < 4; j++) {
            const int cl = wn + j * 8 + 2 * gc;
            float2 v0, v1;
            v0.x = acc[i][j][0] + sbias[cl];
            v0.y = acc[i][j][1] + sbias[cl + 1];
            v1.x = acc[i][j][2] + sbias[cl];
            v1.y = acc[i][j][3] + sbias[cl + 1];
            *reinterpret_cast<float2*>(g_Y + (size_t)r0 * NTOT + n0 + cl) = v0;
            *reinterpret_cast<float2*>(g_Y + (size_t)(r0 + 8) * NTOT + n0 + cl) = v1;
        }
    }
}

// ---------------------------------------------------------------------------
// rel epilogue
// ---------------------------------------------------------------------------
__global__ __launch_bounds__(128) void rel_kernel(
    const int* __restrict__ rel_feats,
    const float* __restrict__ rel_emb,
    const float* __restrict__ bn_w, const float* __restrict__ bn_b,
    const float* __restrict__ bn_rm, const float* __restrict__ bn_rv,
    float* __restrict__ out)
{
    const int row = blockIdx.x;
    const int g = threadIdx.x;
    __shared__ int srel[20];
    if (g < 20) srel[g] = rel_feats[(size_t)row * 20 + g];
    __syncthreads();

    float msum = 0.f;
    float a0 = 0.f, a1 = 0.f, a2 = 0.f, a3 = 0.f;
    #pragma unroll
    for (int j = 0; j < 20; j++) {
        int r = srel[j];
        if (r > 0) {
            msum += 1.f;
            const float* e = rel_emb + (size_t)r * GDIM;
            a0 += e[g];
            a1 += e[g + 128];
            a2 += e[g + 256];
            a3 += e[g + 384];
        }
    }

    const int c = row % FO;
    const float inv = bn_w[c] / sqrtf(bn_rv[c] + BN_EPS);
    const float rmv = bn_rm[c], bbv = bn_b[c];
    const float* yrow = g_Y + (size_t)row * NTOT;
    float* orow = out + (size_t)row * NTOT;

    float accs[4] = {a0, a1, a2, a3};
    #pragma unroll
    for (int i = 0; i < 4; i++) {
        int gg = g + i * 128;
        float val = (accs[i] + yrow[gg] * msum) / msum;
        float t = tanhf(val);
        orow[gg] = (t - rmv) * inv + bbv;
    }
}

// ===========================================================================
// GEMM2 (mma.sync tf32, BK=40 = 520/13 -> 13 k-tiles, 5x fewer barriers)
//   C[m,n] = sum_k tem[b][m,k] * g_Y_tem[b*520+k, n]
// Block 64x128, 3-stage cp.async (dynamic smem 97KB -> 2 CTAs/SM),
// 256 thr (8 warps 2x4, warp tile 32x32), 5 k8-slices per k-tile.
// ===========================================================================
#define G2_BM 64
#define G2_BN 128
#define G2_BK 40
#define G2_STAGES 3
#define G2_LDA 44
#define G2_LDB 136
#define G2_ASTG (G2_BM * G2_LDA)     // 2816 floats
#define G2_BSTG (G2_BK * G2_LDB)     // 5440 floats
#define G2_KT 13                      // 13 * 40 = 520

__global__ __launch_bounds__(256) void gemm2_mma_kernel(
    const float* __restrict__ tem,
    const float* __restrict__ bn_w, const float* __restrict__ bn_b,
    const float* __restrict__ bn_rm, const float* __restrict__ bn_rv,
    float* __restrict__ out)
{
    extern __shared__ float sm2[];
    float* As = sm2;                            // [STAGES][64][44]
    float* Bs = sm2 + G2_STAGES * G2_ASTG;      // [STAGES][40][136]

    const int b  = blockIdx.z;
    const int m0 = blockIdx.y * G2_BM;
    const int nb0 = blockIdx.x * G2_BN;

    const int tid  = threadIdx.x;
    const int wid  = tid >> 5;
    const int lane = tid & 31;

    // A staging: thread t -> rows (t>>3) and (t>>3)+32; chunk c = t&7 (+8 if c<2)
    const int aR  = tid >> 3;              // 0..31
    const int aC  = tid & 7;               // 0..7
    const int aR0 = (m0 + aR      < FO) ? (m0 + aR)      : (FO - 1);
    const int aR1 = (m0 + aR + 32 < FO) ? (m0 + aR + 32) : (FO - 1);
    const float* gA0 = tem + (size_t)b * FO * FO + (size_t)aR0 * FO + aC * 4;
    const float* gA1 = tem + (size_t)b * FO * FO + (size_t)aR1 * FO + aC * 4;
    const uint32_t sA0 = smem_u32(As) + ((aR * G2_LDA + aC * 4) << 2);
    const uint32_t sA1 = smem_u32(As) + (((aR + 32) * G2_LDA + aC * 4) << 2);

    // B staging: thread t -> rows (t>>5)+8p, p=0..4; chunk cb = t&31
    const int bR = tid >> 5;               // 0..7
    const int cb = tid & 31;
    const float* gB = g_Y + GDIM + nb0 + cb * 4
                      + (size_t)(b * FO + bR) * NTOT;
    const uint32_t sB = smem_u32(Bs) + ((bR * G2_LDB + cb * 4) << 2);

    const uint32_t aStg = G2_ASTG << 2;
    const uint32_t bStg = G2_BSTG << 2;

    const int wm = (wid >> 2) * 32;
    const int wn = (wid & 3) * 32;
    const int gr = lane >> 2;
    const int gc = lane & 3;

    uint32_t aoff[2];
    #pragma unroll
    for (int i = 0; i < 2; i++)
        aoff[i] = (uint32_t)(((wm + i * 16 + (lane & 15)) * G2_LDA
                              + ((lane >> 4) << 2)) << 2);
    const uint32_t aSm = smem_u32(As);

    float acc[2][4][4];
    #pragma unroll
    for (int i = 0; i < 2; i++)
        #pragma unroll
        for (int j = 0; j < 4; j++)
            #pragma unroll
            for (int r = 0; r < 4; r++) acc[i][j][r] = 0.f;

    // Stage loader (k0 = kt*40)
    auto load_stage = [&](int s, int kt) {
        const int k0 = kt * G2_BK;
        // A: rows aR, aR+32; chunks aC and (aC<2 ? aC+8 : none)
        CP_ASYNC16(sA0 + s * aStg, gA0 + k0);
        CP_ASYNC16(sA1 + s * aStg, gA1 + k0);
        if (aC < 2) {
            CP_ASYNC16(sA0 + s * aStg + 128, gA0 + k0 + 32);
            CP_ASYNC16(sA1 + s * aStg + 128, gA1 + k0 + 32);
        }
        // B: 5 row passes
        #pragma unroll
        for (int p = 0; p < 5; p++)
            CP_ASYNC16(sB + s * bStg + p * 8 * (G2_LDB << 2),
                       gB + (size_t)(k0 + p * 8) * NTOT);
    };

    #pragma unroll
    for (int s = 0; s < G2_STAGES - 1; s++) {
        load_stage(s, s);
        CP_COMMIT();
    }

    #pragma unroll 1
    for (int kt = 0; kt < G2_KT; kt++) {
        CP_WAIT(G2_STAGES - 2);
        __syncthreads();

        if (kt + G2_STAGES - 1 < G2_KT)
            load_stage((kt + G2_STAGES - 1) % G2_STAGES, kt + G2_STAGES - 1);
        CP_COMMIT();

        const int s = kt % G2_STAGES;
        const uint32_t aBase = aSm + s * aStg;
        const uint32_t* Bst = reinterpret_cast<const uint32_t*>(Bs + s * G2_BSTG);

        #pragma unroll
        for (int ks = 0; ks < 5; ks++) {
            const uint32_t kbB = (ks * 8) << 2;
            uint32_t af[2][4];
            #pragma unroll
            for (int i = 0; i < 2; i++)
                LDSM_X4(af[i][0], af[i][1], af[i][2], af[i][3],
                        aBase + aoff[i] + kbB);
            uint32_t bf[4][2];
            #pragma unroll
            for (int j = 0; j < 4; j++) {
                const uint32_t* p = Bst + (ks * 8 + gc) * G2_LDB + wn + j * 8 + gr;
                bf[j][0] = p[0];
                bf[j][1] = p[4 * G2_LDB];
            }
            #pragma unroll
            for (int i = 0; i < 2; i++)
                #pragma unroll
                for (int j = 0; j < 4; j++)
                    mma_tf32(acc[i][j], af[i], bf[j]);
        }
    }

    #pragma unroll
    for (int i = 0; i < 2; i++) {
        #pragma unroll
        for (int half = 0; half < 2; half++) {
            const int m = m0 + wm + i * 16 + gr + half * 8;
            if (m < FO) {
                const float tsum = g_tsum[b * FO + m];
                const float inv = bn_w[m] / sqrtf(bn_rv[m] + BN_EPS);
                const float rmv = bn_rm[m], bbv = bn_b[m];
                float* orow = out + (size_t)(b * FO + m) * NTOT + GDIM + nb0;
                #pragma unroll
                for (int j = 0; j < 4; j++) {
                    const int cl = wn + j * 8 + 2 * gc;
                    float2 v;
                    v.x = (tanhf(acc[i][j][half * 2 + 0] / tsum) - rmv) * inv + bbv;
                    v.y = (tanhf(acc[i][j][half * 2 + 1] / tsum) - rmv) * inv + bbv;
                    *reinterpret_cast<float2*>(orow + cl) = v;
                }
            }
        }
    }
}

// ---------------------------------------------------------------------------
extern "C" void kernel_launch(void* const* d_in, const int* in_sizes, int n_in,
                              void* d_out, int out_size)
{
    const float* region   = (const float*)d_in[0];
    // d_in[1] = region_masks (unused by the reference math)
    const int*   relF     = (const int*)d_in[2];
    const float* tem      = (const float*)d_in[3];
    const float* relW     = (const float*)d_in[4];
    const float* relb     = (const float*)d_in[5];
    const float* rel_emb  = (const float*)d_in[6];
    const float* temW     = (const float*)d_in[7];
    const float* temb     = (const float*)d_in[8];
    const float* bn_w     = (const float*)d_in[9];
    const float* bn_b     = (const float*)d_in[10];
    const float* bn_rm    = (const float*)d_in[11];
    const float* bn_rv    = (const float*)d_in[12];
    float* out = (float*)d_out;

    temsum_kernel<<<MTOT, 128>>>(tem);

    const int g1_smem = G1_STAGES * G1_STG_F * 2 * sizeof(float);  // 81920
    cudaFuncSetAttribute(gemm1_mma_kernel,
                         cudaFuncAttributeMaxDynamicSharedMemorySize, g1_smem);

    dim3 g1(NTOT / G1_BN, MTOT / G1_BM);        // (8, 130)
    gemm1_mma_kernel<<<g1, 256, g1_smem>>>(region, relW, relb, temW, temb);

    rel_kernel<<<MTOT, 128>>>(relF, rel_emb, bn_w, bn_b, bn_rm, bn_rv, out);

    const int g2_smem = G2_STAGES * (G2_ASTG + G2_BSTG) * sizeof(float); // 99072
    cudaFuncSetAttribute(gemm2_mma_kernel,
                         cudaFuncAttributeMaxDynamicSharedMemorySize, g2_smem);

    dim3 g2(GDIM / G2_BN, (FO + G2_BM - 1) / G2_BM, 32);   // (4, 9, 32)
    gemm2_mma_kernel<<<g2, 256, g2_smem>>>(tem, bn_w, bn_b, bn_rm, bn_rv, out);
}